// round 13
// baseline (speedup 1.0000x reference)
#include <cuda_runtime.h>

// VQ_86139864089353: per-dimension 1D vector quantization — 3 kernels.
// ze: (B, D, 1) f32 ; e: (K, D) f32.  out: [ z (B*D) f32 | zq (B*D) f32 ]
//
// K1: partial stable ranks (u64 monotone keys), 48 blocks.
// K2: combine+scatter sorted {val,orig}; build ANSWER-LUT: cells wholly
//     inside one robust Voronoi region store the winning sorted index
//     (bit15=0); boundary cells store lower-bound + flag (bit15=1).
// K3: pure cells: 2 LDS. Impure: exact fp32 window argmin (u64 key
//     (dd:orig:c) == reference argmin with first-orig tie-break).

#define BN      262144
#define DDIM    3
#define KK      512
#define NBD     (BN * DDIM)
#define NEL     (BN * DDIM)
#define NCELL   4096
#define FLO     (-4.0f)
#define FW      0.001953125f             // 1/512 (dyadic)
#define FINVW   512.0f
#define EPS     0x1p-16f                 // >> fp32 decision sliver & map slop
#define JPARTS  16
#define JCH     (KK / JPARTS)            // 32

#define MBLK    512
#define MVEC    2
#define MGRID   (NEL / (MBLK * MVEC))    // 768

__device__ int            g_rankp[DDIM][JPARTS][KK];
__device__ uint2          g_tab[DDIM][KK];      // {val bits, orig}
__device__ unsigned short g_lut[DDIM][NCELL];

// Monotone (order-preserving) uint32 map of an IEEE754 float.
__device__ __forceinline__ unsigned fkey(float f) {
    unsigned u = __float_as_uint(f);
    return u ^ ((unsigned)((int)u >> 31) | 0x80000000u);
}

// ---------------------------------------------------------------------------
// Kernel 1: partial stable ranks. grid (DDIM, JPARTS) x KK threads.
// ---------------------------------------------------------------------------
__global__ void vq_rank(const float* __restrict__ e) {
    const int d = blockIdx.x;
    const int p = blockIdx.y;
    const int k = threadIdx.x;

    __shared__ unsigned long long s_k[JCH];
    if (k < JCH) {
        int j = p * JCH + k;
        s_k[k] = ((unsigned long long)fkey(e[j * DDIM + d]) << 16) | (unsigned)j;
    }
    __syncthreads();

    const unsigned long long kv =
        ((unsigned long long)fkey(e[k * DDIM + d]) << 16) | (unsigned)k;
    int r = 0;
#pragma unroll
    for (int j = 0; j < JCH; ++j)
        r += (s_k[j] < kv);
    g_rankp[d][p][k] = r;
}

// ---------------------------------------------------------------------------
// Kernel 2: scatter + answer-LUT. grid DDIM x KK threads.
// ---------------------------------------------------------------------------
__global__ void __launch_bounds__(KK)
vq_build(const float* __restrict__ e) {
    const int d = blockIdx.x;
    const int k = threadIdx.x;   // 0..511

    __shared__ float s_sorted[KK];
    __shared__ short s_org[KK];

    int r = 0;
#pragma unroll
    for (int p = 0; p < JPARTS; ++p) r += g_rankp[d][p][k];

    const float v = e[k * DDIM + d];
    s_sorted[r] = v;
    s_org[r]    = (short)k;
    __syncthreads();

    g_tab[d][k] = make_uint2(__float_as_uint(s_sorted[k]), (unsigned)s_org[k]);

    // Per cell: pure (answer index) or impure (lower bound | 0x8000).
    for (int c = k; c < NCELL; c += KK) {
        float xlo = (c == 0)         ? -1.0e30f
                                     : fmaf((float)c, FW, FLO) - EPS;
        float xhi = (c == NCELL - 1) ?  1.0e30f
                                     : fmaf((float)(c + 1), FW, FLO) + EPS;

        // ub(x) = first index with sorted[] > x
        int lo = 0, hi = KK;
        while (lo < hi) {
            int m = (lo + hi) >> 1;
            if (s_sorted[m] <= xlo) lo = m + 1; else hi = m;
        }
        const int i1 = lo;
        lo = i1; hi = KK;
        while (lo < hi) {
            int m = (lo + hi) >> 1;
            if (s_sorted[m] <= xhi) lo = m + 1; else hi = m;
        }
        const int i2 = lo;

        unsigned short entry = (unsigned short)(0x8000u | (unsigned)i1);
        if (i1 == i2) {
            const int i = i1;
            int ans = -1;
            if (i == 0)                              ans = 0;
            else if (i == KK)                        ans = KK - 1;
            else if (s_sorted[i - 1] == s_sorted[i]) ans = i - 1;  // stable tie
            else {
                float mid = 0.5f * (s_sorted[i - 1] + s_sorted[i]);
                if      (xhi < mid - EPS) ans = i - 1;
                else if (xlo > mid + EPS) ans = i;
            }
            if (ans >= 0) entry = (unsigned short)ans;
        }
        g_lut[d][c] = entry;
    }
}

// ---------------------------------------------------------------------------
// Kernel 3: main. 2 elements/thread, 512-thread blocks, grid 768.
// ---------------------------------------------------------------------------
__global__ void __launch_bounds__(MBLK, 4)
vq_main(const float2* __restrict__ ze2, float* __restrict__ out) {
    __shared__ uint2          s_tab[DDIM][KK];       // 12 KB
    __shared__ unsigned short s_lut[DDIM][NCELL];    // 24 KB

    const int tid = threadIdx.x;
    {
        const uint4* src = (const uint4*)g_tab;
        uint4*       dst = (uint4*)s_tab;
        for (int i = tid; i < (int)(DDIM * KK * sizeof(uint2) / 16); i += MBLK)
            dst[i] = src[i];
    }
    {
        const uint4* src = (const uint4*)g_lut;
        uint4*       dst = (uint4*)s_lut;
        for (int i = tid; i < (int)(DDIM * NCELL * sizeof(short) / 16); i += MBLK)
            dst[i] = src[i];
    }
    __syncthreads();

    const int t  = blockIdx.x * MBLK + tid;      // float2 index
    const int n0 = t * MVEC;
    float2 xv = ze2[t];
    float xs[MVEC] = {xv.x, xv.y};
    float rz[MVEC], rq[MVEC];

    int d = n0 % 3;
#pragma unroll
    for (int j = 0; j < MVEC; ++j) {
        const float x = xs[j];
        const uint2* tab = &s_tab[d][0];

        float tt = fminf(fmaxf((x - FLO) * FINVW, 0.0f), (float)(NCELL - 1));
        const unsigned ei = s_lut[d][(int)tt];

        unsigned orig, vbits;
        if (ei & 0x8000u) {
            // ---- impure: exact fp32 window argmin (validated machinery) ----
            int lb = (int)(ei & 0x7fffu);
            int a  = lb < 2 ? 2 : (lb > KK - 3 ? KK - 3 : lb);

            unsigned long long best = ~0ull;
            float w0 = 0.0f, w1 = 0.0f;
#pragma unroll
            for (int u = -2; u <= 2; ++u) {
                int c = a + u;
                uint2 pp = tab[c];
                float vv = __uint_as_float(pp.x);
                float dx = x - vv;
                float dd = dx * dx;              // same fp32 op as reference
                unsigned long long key =
                    ((unsigned long long)__float_as_uint(dd) << 32)
                  | (unsigned long long)(pp.y << 16) | (unsigned)c;
                best = best < key ? best : key;
                if (u == 1) w0 = vv;
                if (u == 2) w1 = vv;
            }
            int c = a + 3;
            while (w0 <= x && c < KK) {          // rare extension
                uint2 pp = tab[c];
                float vv = __uint_as_float(pp.x);
                float dx = x - vv;
                float dd = dx * dx;
                unsigned long long key =
                    ((unsigned long long)__float_as_uint(dd) << 32)
                  | (unsigned long long)(pp.y << 16) | (unsigned)c;
                best = best < key ? best : key;
                w0 = w1; w1 = vv; ++c;
            }
            int cwin = (int)(best & 0xFFFFu);
            orig  = (unsigned)((best >> 16) & 0xFFFFu);
            vbits = tab[cwin].x;
        } else {
            // ---- pure: direct answer ----
            uint2 pp = tab[ei];
            orig  = pp.y;
            vbits = pp.x;
        }

        rz[j] = (float)orig;
        rq[j] = __uint_as_float(vbits);

        d = (d == 2) ? 0 : d + 1;
    }

    ((float2*)out)[t]         = make_float2(rz[0], rz[1]);
    ((float2*)(out + NBD))[t] = make_float2(rq[0], rq[1]);
}

// ---------------------------------------------------------------------------
extern "C" void kernel_launch(void* const* d_in, const int* in_sizes, int n_in,
                              void* d_out, int out_size) {
    const float* ze = (const float*)d_in[0];   // (B, D, 1)
    const float* e  = (const float*)d_in[1];   // (K, D)
    float* out = (float*)d_out;

    vq_rank<<<dim3(DDIM, JPARTS), KK>>>(e);
    vq_build<<<DDIM, KK>>>(e);
    vq_main<<<MGRID, MBLK>>>((const float2*)ze, out);
}

// round 14
// speedup vs baseline: 1.3251x; 1.3251x over previous
#include <cuda_runtime.h>

// VQ_86139864089353: per-dimension 1D vector quantization — 3 kernels.
// ze: (B, D, 1) f32 ; e: (K, D) f32.  out: [ z (B*D) f32 | zq (B*D) f32 ]
//
// R6-validated pipeline; vq_main now uses 1024-thread blocks (grid 384) to
// halve the per-block table broadcast (L2->SMEM) cost at equal occupancy.

#define BN      262144
#define DDIM    3
#define KK      512
#define NBD     (BN * DDIM)
#define NEL     (BN * DDIM)
#define NCELL   2048
#define FLO     (-4.0f)
#define FW      (8.0f / (float)NCELL)    // 1/256 (dyadic)
#define FINVW   ((float)NCELL / 8.0f)    // 256   (dyadic)
#define JPARTS  16
#define JCH     (KK / JPARTS)            // 32

#define MBLK    1024
#define MVEC    2
#define MGRID   (NEL / (MBLK * MVEC))    // 384

__device__ int            g_rankp[DDIM][JPARTS][KK];
__device__ float2         g_pair[DDIM][KK];    // {sorted value, (float)orig}
__device__ unsigned short g_lut[DDIM][NCELL];

// Monotone (order-preserving) uint32 map of an IEEE754 float.
__device__ __forceinline__ unsigned fkey(float f) {
    unsigned u = __float_as_uint(f);
    return u ^ ((unsigned)((int)u >> 31) | 0x80000000u);
}

// ---------------------------------------------------------------------------
// Kernel 1: partial stable ranks via 64-bit keys. grid (DDIM, JPARTS) x 512.
// key = mono(value):index  ->  (kj < kk) == (vj<vk || (vj==vk && j<k))
// ---------------------------------------------------------------------------
__global__ void vq_rank(const float* __restrict__ e) {
    const int d = blockIdx.x;
    const int p = blockIdx.y;
    const int k = threadIdx.x;

    __shared__ unsigned long long s_k[JCH];
    if (k < JCH) {
        int j = p * JCH + k;
        s_k[k] = ((unsigned long long)fkey(e[j * DDIM + d]) << 16) | (unsigned)j;
    }
    __syncthreads();

    const unsigned long long kv =
        ((unsigned long long)fkey(e[k * DDIM + d]) << 16) | (unsigned)k;
    int r = 0;
#pragma unroll
    for (int j = 0; j < JCH; ++j)
        r += (s_k[j] < kv);
    g_rankp[d][p][k] = r;
}

// ---------------------------------------------------------------------------
// Kernel 2: combine partials, scatter to sorted order, LUT. grid DDIM x KK.
// ---------------------------------------------------------------------------
__global__ void vq_build(const float* __restrict__ e) {
    const int d = blockIdx.x;
    const int k = threadIdx.x;   // 0..511

    int r = 0;
#pragma unroll
    for (int p = 0; p < JPARTS; ++p)
        r += g_rankp[d][p][k];

    __shared__ float s_sorted[KK];
    __shared__ short s_org[KK];
    s_sorted[r] = e[k * DDIM + d];
    s_org[r]    = (short)k;
    __syncthreads();

    g_pair[d][k] = make_float2(s_sorted[k], (float)s_org[k]);

    // LUT: conservative lower bound on insertion position, one-cell guard.
    for (int c = k; c < NCELL; c += KK) {
        float edge = FLO + (float)c * FW - FW;
        int lo = 0, hi = KK;
        while (lo < hi) {
            int m = (lo + hi) >> 1;
            if (s_sorted[m] < edge) lo = m + 1; else hi = m;
        }
        g_lut[d][c] = (unsigned short)lo;
    }
}

// ---------------------------------------------------------------------------
// Kernel 3: main. 2 elements/thread, 1024-thread blocks, grid 384.
// ---------------------------------------------------------------------------
__global__ void __launch_bounds__(MBLK, 2)
vq_main(const float2* __restrict__ ze2, float* __restrict__ out) {
    __shared__ float2         s_pair[DDIM][KK];      // 12 KB
    __shared__ unsigned short s_lut[DDIM][NCELL];    // 12 KB

    const int tid = threadIdx.x;
    {
        const float4* src = (const float4*)g_pair;
        float4*       dst = (float4*)s_pair;
        for (int i = tid; i < (int)(DDIM * KK * sizeof(float2) / 16); i += MBLK)
            dst[i] = src[i];
    }
    {
        const uint4* src = (const uint4*)g_lut;
        uint4*       dst = (uint4*)s_lut;
        for (int i = tid; i < (int)(DDIM * NCELL * sizeof(short) / 16); i += MBLK)
            dst[i] = src[i];
    }
    __syncthreads();

    const int t  = blockIdx.x * MBLK + tid;      // float2 index
    const int n0 = t * MVEC;
    float2 xv = ze2[t];
    float xs[MVEC] = {xv.x, xv.y};
    float rz[MVEC], rq[MVEC];

    int d = n0 % 3;
#pragma unroll
    for (int j = 0; j < MVEC; ++j) {
        const float x = xs[j];

        float tt = fminf(fmaxf((x - FLO) * FINVW, 0.0f), (float)(NCELL - 1));
        int i = s_lut[d][(int)tt];
        while (i < KK && s_pair[d][i].x <= x) ++i;

        // exact fp32 argmin over sorted window [i-2, i+1], tie -> min orig
        float bestD = __int_as_float(0x7f800000);
        float bestO = 1.0e9f;
        float bestV = 0.0f;
#pragma unroll
        for (int off = -2; off <= 1; ++off) {
            int c = i + off;
            c = c < 0 ? 0 : (c > KK - 1 ? KK - 1 : c);
            float2 p = s_pair[d][c];
            float dx = x - p.x;
            float dd = dx * dx;                  // same fp32 op as reference
            bool take = (dd < bestD) || (dd == bestD && p.y < bestO);
            bestD = take ? dd : bestD;
            bestO = take ? p.y : bestO;
            bestV = take ? p.x : bestV;
        }
        rz[j] = bestO;
        rq[j] = bestV;

        d = (d == 2) ? 0 : d + 1;
    }

    ((float2*)out)[t]         = make_float2(rz[0], rz[1]);
    ((float2*)(out + NBD))[t] = make_float2(rq[0], rq[1]);
}

// ---------------------------------------------------------------------------
extern "C" void kernel_launch(void* const* d_in, const int* in_sizes, int n_in,
                              void* d_out, int out_size) {
    const float* ze = (const float*)d_in[0];   // (B, D, 1)
    const float* e  = (const float*)d_in[1];   // (K, D)
    float* out = (float*)d_out;

    vq_rank<<<dim3(DDIM, JPARTS), KK>>>(e);
    vq_build<<<DDIM, KK>>>(e);
    vq_main<<<MGRID, MBLK>>>((const float2*)ze, out);
}